// round 4
// baseline (speedup 1.0000x reference)
#include <cuda_runtime.h>
#include <cstdint>

// Morton helper: spread low 16 bits of x into even bit positions.
__device__ __forceinline__ unsigned part1by1(unsigned x) {
    x &= 0x0000ffffu;
    x = (x | (x << 8)) & 0x00FF00FFu;
    x = (x | (x << 4)) & 0x0F0F0F0Fu;
    x = (x | (x << 2)) & 0x33333333u;
    x = (x | (x << 1)) & 0x55555555u;
    return x;
}

// Replica of the XLA-lowered index path.
// KEY: XLA's algebraic simplifier rewrites division-by-constant into
// multiplication by the f32-rounded reciprocal. We therefore multiply by
// correctly-rounded reciprocals instead of dividing. All ops pinned to IEEE
// rn intrinsics (immune to --use_fast_math). rintf == jnp.round
// (round-half-to-even); C cast == astype(int32) (truncate toward zero).
__device__ __forceinline__ int quad_index(float px, float py) {
    const float SCALE   = 10000000.0f;          // 1e7, exact in f32
    const float R_SCALE = 1.0f / 10000000.0f;   // f32 correctly-rounded 1e-7
    const float R_W     = 1.0f / 360.0f;        // f32 correctly-rounded
    const float R_H     = 1.0f / 180.0f;        // f32 correctly-rounded

    float cx = __fmul_rn(rintf(__fmul_rn(px, SCALE)), R_SCALE);
    float cy = __fmul_rn(rintf(__fmul_rn(py, SCALE)), R_SCALE);
    float u  = __fmul_rn(__fadd_rn(cx, 180.0f), R_W);
    float v  = __fmul_rn(__fadd_rn(cy,  90.0f), R_H);
    int ix = (int)__fmul_rn(u, 512.0f);   // *512 is a pow2 scale: commutes with
    int iy = (int)__fmul_rn(v, 512.0f);   // rounding, so any XLA const-folding
    ix = min(max(ix, 0), 511);            // of (1/W)*512 is bit-identical.
    iy = min(max(iy, 0), 511);
    return (int)(part1by1((unsigned)ix) | (part1by1((unsigned)iy) << 1));
}

// 4 points per thread: 2x float4 coord loads, 1x float4 x load, 1x float4 store.
__global__ void __launch_bounds__(256)
quadpool_kernel(const float4* __restrict__ in4,   // [n/2] float4 == [n] float2
                const float4* __restrict__ x4,    // [n/4]
                const float*  __restrict__ w,     // [262144]
                const float*  __restrict__ b,     // [262144]
                float4* __restrict__ out4,        // [n/4]
                int n4)
{
    int i = blockIdx.x * blockDim.x + threadIdx.x;
    if (i >= n4) return;

    float4 p01 = in4[2 * i];       // points 0,1: (x0,y0,x1,y1)
    float4 p23 = in4[2 * i + 1];   // points 2,3
    float4 xv  = x4[i];

    int i0 = quad_index(p01.x, p01.y);
    int i1 = quad_index(p01.z, p01.w);
    int i2 = quad_index(p23.x, p23.y);
    int i3 = quad_index(p23.z, p23.w);

    float w0 = __ldg(&w[i0]), b0 = __ldg(&b[i0]);
    float w1 = __ldg(&w[i1]), b1 = __ldg(&b[i1]);
    float w2 = __ldg(&w[i2]), b2 = __ldg(&b[i2]);
    float w3 = __ldg(&w[i3]), b3 = __ldg(&b[i3]);

    float4 o;
    o.x = fmaf(w0, xv.x, b0);
    o.y = fmaf(w1, xv.y, b1);
    o.z = fmaf(w2, xv.z, b2);
    o.w = fmaf(w3, xv.w, b3);
    out4[i] = o;
}

// Scalar tail (n not divisible by 4 — not expected here, but safe).
__global__ void quadpool_tail_kernel(const float2* __restrict__ in2,
                                     const float*  __restrict__ x,
                                     const float*  __restrict__ w,
                                     const float*  __restrict__ b,
                                     float* __restrict__ out,
                                     int start, int n)
{
    int i = start + blockIdx.x * blockDim.x + threadIdx.x;
    if (i >= n) return;
    float2 p = in2[i];
    int idx = quad_index(p.x, p.y);
    out[i] = fmaf(__ldg(&w[idx]), x[i], __ldg(&b[idx]));
}

extern "C" void kernel_launch(void* const* d_in, const int* in_sizes, int n_in,
                              void* d_out, int out_size)
{
    const float* in  = (const float*)d_in[0];   // [N,2]
    const float* x   = (const float*)d_in[1];   // [N]
    const float* w   = (const float*)d_in[2];   // [262144]
    const float* b   = (const float*)d_in[3];   // [262144]
    float* out = (float*)d_out;

    int n  = in_sizes[1];        // N points
    int n4 = n >> 2;
    if (n4 > 0) {
        int threads = 256;
        int blocks = (n4 + threads - 1) / threads;
        quadpool_kernel<<<blocks, threads>>>(
            (const float4*)in, (const float4*)x, w, b, (float4*)out, n4);
    }
    int done = n4 << 2;
    int rem = n - done;
    if (rem > 0) {
        quadpool_tail_kernel<<<(rem + 255) / 256, 256>>>(
            (const float2*)in, x, w, b, out, done, n);
    }
}

// round 6
// speedup vs baseline: 1.3868x; 1.3868x over previous
#include <cuda_runtime.h>
#include <cstdint>

#define TABLE_N 262144

// Scratch: interleaved (weight, bias) table. Static __device__ global — no
// allocation. Rebuilt every kernel_launch (deterministic, graph-capturable).
__device__ __align__(16) float2 g_wb[TABLE_N];

// Pack w[] and b[] into interleaved float2 pairs, float4-vectorized.
__global__ void __launch_bounds__(256)
pack_wb_kernel(const float4* __restrict__ w4, const float4* __restrict__ b4)
{
    int i = blockIdx.x * blockDim.x + threadIdx.x;   // [0, TABLE_N/4)
    if (i >= TABLE_N / 4) return;
    float4 w = w4[i];
    float4 b = b4[i];
    float4* dst = reinterpret_cast<float4*>(&g_wb[4 * i]);
    dst[0] = make_float4(w.x, b.x, w.y, b.y);
    dst[1] = make_float4(w.z, b.z, w.w, b.w);
}

// Morton helper: spread low 16 bits into even bit positions.
__device__ __forceinline__ unsigned part1by1(unsigned x) {
    x &= 0x0000ffffu;
    x = (x | (x << 8)) & 0x00FF00FFu;
    x = (x | (x << 4)) & 0x0F0F0F0Fu;
    x = (x | (x << 2)) & 0x33333333u;
    x = (x | (x << 1)) & 0x55555555u;
    return x;
}

// XLA-lowered index path: division-by-constant becomes multiply by the
// f32-rounded reciprocal. All ops pinned to IEEE rn intrinsics.
__device__ __forceinline__ int quad_index(float px, float py) {
    const float SCALE   = 10000000.0f;
    const float R_SCALE = 1.0f / 10000000.0f;
    const float R_W     = 1.0f / 360.0f;
    const float R_H     = 1.0f / 180.0f;

    float cx = __fmul_rn(rintf(__fmul_rn(px, SCALE)), R_SCALE);
    float cy = __fmul_rn(rintf(__fmul_rn(py, SCALE)), R_SCALE);
    float u  = __fmul_rn(__fadd_rn(cx, 180.0f), R_W);
    float v  = __fmul_rn(__fadd_rn(cy,  90.0f), R_H);
    int ix = (int)__fmul_rn(u, 512.0f);
    int iy = (int)__fmul_rn(v, 512.0f);
    ix = min(max(ix, 0), 511);
    iy = min(max(iy, 0), 511);
    return (int)(part1by1((unsigned)ix) | (part1by1((unsigned)iy) << 1));
}

// 4 points/thread; ONE float2 gather per point from the packed table.
__global__ void __launch_bounds__(256)
quadpool_kernel(const float4* __restrict__ in4,   // [2*n4] == [n] float2
                const float4* __restrict__ x4,    // [n4]
                float4* __restrict__ out4,        // [n4]
                int n4)
{
    int i = blockIdx.x * blockDim.x + threadIdx.x;
    if (i >= n4) return;

    float4 p01 = in4[2 * i];
    float4 p23 = in4[2 * i + 1];
    float4 xv  = x4[i];

    int i0 = quad_index(p01.x, p01.y);
    int i1 = quad_index(p01.z, p01.w);
    int i2 = quad_index(p23.x, p23.y);
    int i3 = quad_index(p23.z, p23.w);

    float2 wb0 = g_wb[i0];
    float2 wb1 = g_wb[i1];
    float2 wb2 = g_wb[i2];
    float2 wb3 = g_wb[i3];

    float4 o;
    o.x = fmaf(wb0.x, xv.x, wb0.y);
    o.y = fmaf(wb1.x, xv.y, wb1.y);
    o.z = fmaf(wb2.x, xv.z, wb2.y);
    o.w = fmaf(wb3.x, xv.w, wb3.y);
    out4[i] = o;
}

// Scalar tail (n not divisible by 4 — not expected, but safe).
__global__ void quadpool_tail_kernel(const float2* __restrict__ in2,
                                     const float*  __restrict__ x,
                                     float* __restrict__ out,
                                     int start, int n)
{
    int i = start + blockIdx.x * blockDim.x + threadIdx.x;
    if (i >= n) return;
    float2 p = in2[i];
    float2 wb = g_wb[quad_index(p.x, p.y)];
    out[i] = fmaf(wb.x, x[i], wb.y);
}

extern "C" void kernel_launch(void* const* d_in, const int* in_sizes, int n_in,
                              void* d_out, int out_size)
{
    const float* in  = (const float*)d_in[0];   // [N,2]
    const float* x   = (const float*)d_in[1];   // [N]
    const float* w   = (const float*)d_in[2];   // [262144]
    const float* b   = (const float*)d_in[3];   // [262144]
    float* out = (float*)d_out;

    // Build packed (w,b) table: 65536 float4-quads, 256 blocks x 256 threads.
    pack_wb_kernel<<<TABLE_N / 4 / 256, 256>>>((const float4*)w, (const float4*)b);

    int n  = in_sizes[1];
    int n4 = n >> 2;
    if (n4 > 0) {
        int threads = 256;
        int blocks = (n4 + threads - 1) / threads;
        quadpool_kernel<<<blocks, threads>>>(
            (const float4*)in, (const float4*)x, (float4*)out, n4);
    }
    int done = n4 << 2;
    int rem = n - done;
    if (rem > 0) {
        quadpool_tail_kernel<<<(rem + 255) / 256, 256>>>(
            (const float2*)in, x, out, done, n);
    }
}